// round 7
// baseline (speedup 1.0000x reference)
#include <cuda_runtime.h>
#include <cstdint>
#include <math.h>

#define T_TOTAL 65536
#define T_BATCH 8192
#define CH 256
#define MEL 640

// ---------------- scratch (__device__ globals) ------------------------------
__device__ float g_h[(size_t)T_TOTAL * CH];      // fp32 residual
__device__ float g_hT[(size_t)T_TOTAL * CH];     // tf32-rounded shadow of h
__device__ float g_acts[(size_t)T_TOTAL * CH];   // tf32-rounded
__device__ float g_skip[(size_t)T_TOTAL * CH];   // fp32
__device__ float g_spectT[(size_t)T_TOTAL * MEL];// tf32-rounded spect
__device__ float g_wTA[(size_t)8 * 512 * 1408];  // [layer][n][k] tf32
__device__ float g_wTB[(size_t)7 * 512 * 256];   // [layer][n][k] tf32
__device__ float g_wTL[(size_t)256 * 256];       // [n][k] tf32

// ---------------- helpers ---------------------------------------------------
__device__ __forceinline__ uint32_t smem_u32(const void* p) {
    uint32_t a;
    asm("{ .reg .u64 t; cvta.to.shared.u64 t, %1; cvt.u32.u64 %0, t; }" : "=r"(a) : "l"(p));
    return a;
}
__device__ __forceinline__ uint32_t f2tf(float x) {
    uint32_t r; asm("cvt.rna.tf32.f32 %0, %1;" : "=r"(r) : "f"(x)); return r;
}
__device__ __forceinline__ float rtf(float x) { return __uint_as_float(f2tf(x)); }

#define CP16(dst, src, sz) \
    asm volatile("cp.async.cg.shared.global [%0], [%1], 16, %2;" \
        :: "r"(dst), "l"(src), "r"(sz) : "memory")
#define CP_COMMIT() asm volatile("cp.async.commit_group;" ::: "memory")
#define CP_WAIT(n)  asm volatile("cp.async.wait_group %0;" :: "n"(n) : "memory")

__device__ __forceinline__ void mma8(float* d, const uint32_t* a, const uint32_t* b) {
    asm volatile(
        "mma.sync.aligned.m16n8k8.row.col.f32.tf32.tf32.f32 "
        "{%0,%1,%2,%3}, {%4,%5,%6,%7}, {%8,%9}, {%0,%1,%2,%3};"
        : "+f"(d[0]), "+f"(d[1]), "+f"(d[2]), "+f"(d[3])
        : "r"(a[0]), "r"(a[1]), "r"(a[2]), "r"(a[3]), "r"(b[0]), "r"(b[1]));
}

#define AST 36   // smem row stride in floats (32 k + 4 pad)

// ---- big-tile layout (layerA / layerB): A 128 rows, B 256 rows -------------
#define OFF_A2(buf) ((buf) * 55296)
#define OFF_B2(buf) (18432 + (buf) * 55296)
#define OFF_BIAS2   110592
#define SMEM_AB2    112640

// ---- small layout (layerL): A 128 rows, B 128 rows -------------------------
#define OFFL_A(buf) ((buf) * 36864)
#define OFFL_B(buf) (18432 + (buf) * 36864)
#define OFFL_BIAS   73728
#define SMEM_L      75776

// ---------------------------------------------------------------------------
// start: h = audio @ start_w + start_b ; hT = tf32(h) ; skip = 0
// ---------------------------------------------------------------------------
__global__ void start_kernel(const float* __restrict__ audio,
                             const float* __restrict__ sw,
                             const float* __restrict__ sb) {
    int idx = blockIdx.x * blockDim.x + threadIdx.x;
    int t = idx >> 8;
    int c = idx & 255;
    float4 a = *(const float4*)&audio[(size_t)t * 4];
    float v = sb[c] + a.x * sw[c] + a.y * sw[256 + c] + a.z * sw[512 + c] + a.w * sw[768 + c];
    g_h[idx] = v;
    g_hT[idx] = rtf(v);
    g_skip[idx] = 0.f;
}

__global__ void round_spect_kernel(const float* __restrict__ spect) {
    size_t idx = (size_t)blockIdx.x * blockDim.x + threadIdx.x;
    g_spectT[idx] = rtf(spect[idx]);
}

// weight transposes: [k][n] -> [n][k], tf32-rounded
__global__ void transA_kernel(const float* __restrict__ in_w, const float* __restrict__ cond_w) {
    size_t idx = (size_t)blockIdx.x * blockDim.x + threadIdx.x;   // 8*512*1408
    int k = (int)(idx % 1408);
    size_t t = idx / 1408;
    int n = (int)(t % 512);
    int l = (int)(t / 512);
    float v;
    if (k < 768)
        v = in_w[(((size_t)l * 3 + (k >> 8)) * 256 + (k & 255)) * 512 + n];
    else
        v = cond_w[((size_t)l * 640 + (k - 768)) * 512 + n];
    g_wTA[idx] = rtf(v);
}
__global__ void transB_kernel(const float* __restrict__ rsw) {
    size_t idx = (size_t)blockIdx.x * blockDim.x + threadIdx.x;   // 7*512*256
    int k = (int)(idx & 255);
    size_t t = idx >> 8;
    int n = (int)(t % 512);
    int l = (int)(t / 512);
    g_wTB[idx] = rtf(rsw[((size_t)l * 256 + k) * 512 + n]);
}
__global__ void transL_kernel(const float* __restrict__ rlw) {
    int idx = blockIdx.x * blockDim.x + threadIdx.x;              // 256*256
    int k = idx & 255;
    int n = idx >> 8;
    g_wTL[idx] = rtf(rlw[k * 256 + n]);
}

// ---------------------------------------------------------------------------
// big-tile compute: warp tile 64 (M) x 64 (B-rows), d[4][8][4]
// As: 128 rows x 32 k ; Bs: 256 rows x 32 k (pair-interleaved halves)
// ---------------------------------------------------------------------------
__device__ __forceinline__ void compute_stage2(const float* As, const float* Bs,
                                               int wm, int wn, int lane,
                                               float d[4][8][4]) {
    const int ar = lane >> 2;
    const int ac = lane & 3;
    #pragma unroll
    for (int q = 0; q < 4; q++) {
        const int k0 = q * 8;
        uint32_t a[4][4];
        #pragma unroll
        for (int mi = 0; mi < 4; mi++) {
            int mb = wm * 64 + mi * 16 + ar;
            a[mi][0] = __float_as_uint(As[mb * AST + k0 + ac]);
            a[mi][1] = __float_as_uint(As[(mb + 8) * AST + k0 + ac]);
            a[mi][2] = __float_as_uint(As[mb * AST + k0 + ac + 4]);
            a[mi][3] = __float_as_uint(As[(mb + 8) * AST + k0 + ac + 4]);
        }
        #pragma unroll
        for (int ni = 0; ni < 8; ni++) {
            int nb = wn * 64 + ni * 8 + ar;
            uint32_t b[2];
            b[0] = __float_as_uint(Bs[nb * AST + k0 + ac]);
            b[1] = __float_as_uint(Bs[nb * AST + k0 + ac + 4]);
            #pragma unroll
            for (int mi = 0; mi < 4; mi++) mma8(d[mi][ni], a[mi], b);
        }
    }
}

// ---------------------------------------------------------------------------
// layer A: x = conv(h)+cond+biases ; acts = tf32(tanh(xa)*sigmoid(xb))
// CTA: 128 tokens x 256 B-rows (=128 act cols, halves interleaved). grid (512,2)
// ---------------------------------------------------------------------------
__global__ void __launch_bounds__(256, 1) layerA_mma(
    const float* __restrict__ in_b, const float* __restrict__ cond_b,
    int layer, int dil) {
    extern __shared__ char smem[];
    const uint32_t sbase = smem_u32(smem);
    const int tid = threadIdx.x;
    const int lane = tid & 31;
    const int wid = tid >> 5;
    const int wm = wid >> 2;     // 0..1
    const int wn = wid & 3;      // 0..3
    const int row0 = blockIdx.x * 128;
    const int n0 = blockIdx.y * 128;      // act-col base (0 or 128)
    const float* __restrict__ wT = g_wTA + (size_t)layer * 512 * 1408;

    {   // biases (full 512 of this layer)
        float* bsm = (float*)(smem + OFF_BIAS2);
        bsm[tid] = in_b[layer * 512 + tid] + cond_b[layer * 512 + tid];
        bsm[256 + tid] = in_b[layer * 512 + 256 + tid] + cond_b[layer * 512 + 256 + tid];
    }

    auto load_stage = [&](int s, int buf) {
        const int kk0 = s * 32;
        const uint32_t abase = sbase + OFF_A2(buf);
        const uint32_t bbase = sbase + OFF_B2(buf);
        if (kk0 < 768) {
            const int tap = kk0 >> 8, kc = kk0 & 255;
            const int shift = (tap - 1) * dil;
            #pragma unroll
            for (int i = 0; i < 4; i++) {
                int v = tid + i * 256;
                int row = v >> 3, c8 = v & 7;
                int r = row0 + row;
                int ts = (r & (T_BATCH - 1)) + shift;
                const float* src;
                uint32_t sz;
                if ((unsigned)ts < (unsigned)T_BATCH) {
                    src = g_hT + (size_t)(r + shift) * CH + kc + c8 * 4;
                    sz = 16;
                } else {
                    src = g_hT;
                    sz = 0;
                }
                CP16(abase + row * 144 + c8 * 16, src, sz);
            }
        } else {
            const int km = kk0 - 768;
            #pragma unroll
            for (int i = 0; i < 4; i++) {
                int v = tid + i * 256;
                int row = v >> 3, c8 = v & 7;
                const float* src = g_spectT + (size_t)(row0 + row) * MEL + km + c8 * 4;
                CP16(abase + row * 144 + c8 * 16, src, 16);
            }
        }
        #pragma unroll
        for (int i = 0; i < 8; i++) {
            int v = tid + i * 256;
            int nl = v >> 3, c8 = v & 7;        // nl 0..255
            int ng = n0 + (nl >> 1) + (nl & 1) * 256;  // pair-interleave halves
            const float* src = wT + (size_t)ng * 1408 + kk0 + c8 * 4;
            CP16(bbase + nl * 144 + c8 * 16, src, 16);
        }
        CP_COMMIT();
    };

    float d[4][8][4] = {};

    load_stage(0, 0);
    for (int s = 0; s < 44; s++) {
        if (s + 1 < 44) { load_stage(s + 1, (s + 1) & 1); CP_WAIT(1); }
        else CP_WAIT(0);
        __syncthreads();
        compute_stage2((const float*)(smem + OFF_A2(s & 1)),
                       (const float*)(smem + OFF_B2(s & 1)), wm, wn, lane, d);
        __syncthreads();
    }

    const float* bsm = (const float*)(smem + OFF_BIAS2);
    const int ar = lane >> 2, ac = lane & 3;
    #pragma unroll
    for (int mi = 0; mi < 4; mi++) {
        #pragma unroll
        for (int eh = 0; eh < 2; eh++) {
            const int m = row0 + wm * 64 + mi * 16 + ar + eh * 8;
            #pragma unroll
            for (int ni = 0; ni < 8; ni++) {
                const int j = n0 + wn * 32 + ni * 4 + ac;
                float xa = d[mi][ni][eh * 2 + 0] + bsm[j];
                float xb = d[mi][ni][eh * 2 + 1] + bsm[256 + j];
                g_acts[(size_t)m * CH + j] = rtf(tanhf(xa) * (1.f / (1.f + expf(-xb))));
            }
        }
    }
}

// ---------------------------------------------------------------------------
// layer B: rs = acts@w + b ; h += rs[:, :256] (fp32 + tf32 shadow); skip += rs[:, 256:]
// ---------------------------------------------------------------------------
__global__ void __launch_bounds__(256, 1) layerB_mma(
    const float* __restrict__ rs_b, int layer) {
    extern __shared__ char smem[];
    const uint32_t sbase = smem_u32(smem);
    const int tid = threadIdx.x;
    const int lane = tid & 31;
    const int wid = tid >> 5;
    const int wm = wid >> 2;
    const int wn = wid & 3;
    const int row0 = blockIdx.x * 128;
    const int n0 = blockIdx.y * 128;
    const float* __restrict__ wT = g_wTB + (size_t)layer * 512 * 256;

    {
        float* bsm = (float*)(smem + OFF_BIAS2);
        bsm[tid] = rs_b[layer * 512 + tid];
        bsm[256 + tid] = rs_b[layer * 512 + 256 + tid];
    }

    auto load_stage = [&](int s, int buf) {
        const int kk0 = s * 32;
        const uint32_t abase = sbase + OFF_A2(buf);
        const uint32_t bbase = sbase + OFF_B2(buf);
        #pragma unroll
        for (int i = 0; i < 4; i++) {
            int v = tid + i * 256;
            int row = v >> 3, c8 = v & 7;
            const float* src = g_acts + (size_t)(row0 + row) * CH + kk0 + c8 * 4;
            CP16(abase + row * 144 + c8 * 16, src, 16);
        }
        #pragma unroll
        for (int i = 0; i < 8; i++) {
            int v = tid + i * 256;
            int nl = v >> 3, c8 = v & 7;
            int ng = n0 + (nl >> 1) + (nl & 1) * 256;
            const float* src = wT + (size_t)ng * 256 + kk0 + c8 * 4;
            CP16(bbase + nl * 144 + c8 * 16, src, 16);
        }
        CP_COMMIT();
    };

    float d[4][8][4] = {};

    load_stage(0, 0);
    for (int s = 0; s < 8; s++) {
        if (s + 1 < 8) { load_stage(s + 1, (s + 1) & 1); CP_WAIT(1); }
        else CP_WAIT(0);
        __syncthreads();
        compute_stage2((const float*)(smem + OFF_A2(s & 1)),
                       (const float*)(smem + OFF_B2(s & 1)), wm, wn, lane, d);
        __syncthreads();
    }

    const float* bsm = (const float*)(smem + OFF_BIAS2);
    const int ar = lane >> 2, ac = lane & 3;
    #pragma unroll
    for (int mi = 0; mi < 4; mi++) {
        #pragma unroll
        for (int eh = 0; eh < 2; eh++) {
            const int m = row0 + wm * 64 + mi * 16 + ar + eh * 8;
            #pragma unroll
            for (int ni = 0; ni < 8; ni++) {
                const int j = n0 + wn * 32 + ni * 4 + ac;
                const size_t o = (size_t)m * CH + j;
                float hv = g_h[o] + d[mi][ni][eh * 2 + 0] + bsm[j];
                float sv = g_skip[o] + d[mi][ni][eh * 2 + 1] + bsm[256 + j];
                g_h[o] = hv;
                g_hT[o] = rtf(hv);
                g_skip[o] = sv;
            }
        }
    }
}

// ---------------------------------------------------------------------------
// last layer: skip += acts @ res_last_w + res_last_b (N=256)  [R5 structure]
// ---------------------------------------------------------------------------
__device__ __forceinline__ void compute_stageL(const float* As, const float* Bs,
                                               int wm, int wn, int lane,
                                               float d[2][4][4]) {
    const int ar = lane >> 2;
    const int ac = lane & 3;
    #pragma unroll
    for (int q = 0; q < 4; q++) {
        const int k0 = q * 8;
        uint32_t a[2][4];
        #pragma unroll
        for (int mi = 0; mi < 2; mi++) {
            int mb = wm * 32 + mi * 16 + ar;
            a[mi][0] = __float_as_uint(As[mb * AST + k0 + ac]);
            a[mi][1] = __float_as_uint(As[(mb + 8) * AST + k0 + ac]);
            a[mi][2] = __float_as_uint(As[mb * AST + k0 + ac + 4]);
            a[mi][3] = __float_as_uint(As[(mb + 8) * AST + k0 + ac + 4]);
        }
        #pragma unroll
        for (int ni = 0; ni < 4; ni++) {
            int nb = wn * 32 + ni * 8 + ar;
            uint32_t b[2];
            b[0] = __float_as_uint(Bs[nb * AST + k0 + ac]);
            b[1] = __float_as_uint(Bs[nb * AST + k0 + ac + 4]);
            mma8(d[0][ni], a[0], b);
            mma8(d[1][ni], a[1], b);
        }
    }
}

__global__ void __launch_bounds__(256, 2) layerL_mma(const float* __restrict__ rl_b) {
    extern __shared__ char smem[];
    const uint32_t sbase = smem_u32(smem);
    const int tid = threadIdx.x;
    const int lane = tid & 31;
    const int wid = tid >> 5;
    const int wm = wid & 3;
    const int wn = wid >> 2;
    const int row0 = blockIdx.x * 128;
    const int n0 = blockIdx.y * 64;

    {
        float* bsm = (float*)(smem + OFFL_BIAS);
        bsm[tid] = rl_b[tid];
    }

    auto load_stage = [&](int s, int buf) {
        const int kk0 = s * 32;
        const uint32_t abase = sbase + OFFL_A(buf);
        const uint32_t bbase = sbase + OFFL_B(buf);
        #pragma unroll
        for (int i = 0; i < 4; i++) {
            int v = tid + i * 256;
            int row = v >> 3, c8 = v & 7;
            const float* src = g_acts + (size_t)(row0 + row) * CH + kk0 + c8 * 4;
            CP16(abase + row * 144 + c8 * 16, src, 16);
        }
        #pragma unroll
        for (int i = 0; i < 2; i++) {
            int v = tid + i * 256;
            int nl = v >> 3, c8 = v & 7;   // nl 0..63
            const float* src = g_wTL + (size_t)(n0 + nl) * 256 + kk0 + c8 * 4;
            CP16(bbase + nl * 144 + c8 * 16, src, 16);
        }
        CP_COMMIT();
    };

    float d[2][4][4] = {};

    load_stage(0, 0);
    for (int s = 0; s < 8; s++) {
        if (s + 1 < 8) { load_stage(s + 1, (s + 1) & 1); CP_WAIT(1); }
        else CP_WAIT(0);
        __syncthreads();
        compute_stageL((const float*)(smem + OFFL_A(s & 1)),
                       (const float*)(smem + OFFL_B(s & 1)), wm, wn, lane, d);
        __syncthreads();
    }

    const float* bsm = (const float*)(smem + OFFL_BIAS);
    #pragma unroll
    for (int mi = 0; mi < 2; mi++) {
        #pragma unroll
        for (int eh = 0; eh < 2; eh++) {
            const int m = row0 + wm * 32 + mi * 16 + (lane >> 2) + eh * 8;
            #pragma unroll
            for (int ni = 0; ni < 4; ni++) {
                const int j = n0 + wn * 32 + ni * 8 + (lane & 3) * 2;
                const size_t o = (size_t)m * CH + j;
                float2 sv = *(float2*)&g_skip[o];
                sv.x += d[mi][ni][eh * 2 + 0] + bsm[j];
                sv.y += d[mi][ni][eh * 2 + 1] + bsm[j + 1];
                *(float2*)&g_skip[o] = sv;
            }
        }
    }
}

// ---------------------------------------------------------------------------
// end: out = skip @ end_w + end_b  — one thread per token, ew cached in smem
// ---------------------------------------------------------------------------
__global__ void end_kernel(const float* __restrict__ ew,
                           const float* __restrict__ eb,
                           float* __restrict__ out) {
    __shared__ float ews[2048];
    __shared__ float ebs[8];
    const int tid = threadIdx.x;
    #pragma unroll
    for (int i = 0; i < 8; i++) ews[tid + i * 256] = ew[tid + i * 256];
    if (tid < 8) ebs[tid] = eb[tid];
    __syncthreads();

    const int t = blockIdx.x * blockDim.x + tid;
    const float* s = &g_skip[(size_t)t * CH];
    float acc[8];
    #pragma unroll
    for (int o = 0; o < 8; o++) acc[o] = ebs[o];
    for (int c = 0; c < CH; c += 4) {
        float4 sv = *(const float4*)&s[c];
        #pragma unroll
        for (int e = 0; e < 4; e++) {
            float svv = (&sv.x)[e];
            const float* w = &ews[(c + e) * 8];
            #pragma unroll
            for (int o = 0; o < 8; o++) acc[o] += svv * w[o];
        }
    }
    float4* op = (float4*)&out[(size_t)t * 8];
    op[0] = make_float4(acc[0], acc[1], acc[2], acc[3]);
    op[1] = make_float4(acc[4], acc[5], acc[6], acc[7]);
}

// ---------------------------------------------------------------------------
extern "C" void kernel_launch(void* const* d_in, const int* in_sizes, int n_in,
                              void* d_out, int out_size) {
    const float* audio      = (const float*)d_in[0];
    const float* spect      = (const float*)d_in[1];
    const float* start_w    = (const float*)d_in[2];
    const float* start_b    = (const float*)d_in[3];
    const float* in_w       = (const float*)d_in[4];
    const float* in_b       = (const float*)d_in[5];
    const float* cond_w     = (const float*)d_in[6];
    const float* cond_b     = (const float*)d_in[7];
    const float* res_skip_w = (const float*)d_in[8];
    const float* res_skip_b = (const float*)d_in[9];
    const float* res_last_w = (const float*)d_in[10];
    const float* res_last_b = (const float*)d_in[11];
    const float* end_w      = (const float*)d_in[12];
    const float* end_b      = (const float*)d_in[13];
    float* out = (float*)d_out;

    static int attr_done = 0;
    if (!attr_done) {
        cudaFuncSetAttribute(layerA_mma, cudaFuncAttributeMaxDynamicSharedMemorySize, SMEM_AB2);
        cudaFuncSetAttribute(layerB_mma, cudaFuncAttributeMaxDynamicSharedMemorySize, SMEM_AB2);
        cudaFuncSetAttribute(layerL_mma, cudaFuncAttributeMaxDynamicSharedMemorySize, SMEM_L);
        attr_done = 1;
    }

    start_kernel<<<(T_TOTAL * CH) / 256, 256>>>(audio, start_w, start_b);
    round_spect_kernel<<<(T_TOTAL / 256) * MEL, 256>>>(spect);
    transA_kernel<<<22528, 256>>>(in_w, cond_w);
    transB_kernel<<<3584, 256>>>(res_skip_w);
    transL_kernel<<<256, 256>>>(res_last_w);

    dim3 g2(512, 2);
    dim3 g4(512, 4);
    for (int l = 0; l < 8; l++) {
        layerA_mma<<<g2, 256, SMEM_AB2>>>(in_b, cond_b, l, 1 << l);
        if (l < 7)
            layerB_mma<<<g2, 256, SMEM_AB2>>>(res_skip_b, l);
        else
            layerL_mma<<<g4, 256, SMEM_L>>>(res_last_b);
    }

    end_kernel<<<T_TOTAL / 256, 256>>>(end_w, end_b, out);
}

// round 9
// speedup vs baseline: 1.0012x; 1.0012x over previous
#include <cuda_runtime.h>
#include <cstdint>
#include <math.h>

#define T_TOTAL 65536
#define T_BATCH 8192
#define CH 256
#define MEL 640

// ---------------- scratch (__device__ globals) ------------------------------
__device__ float g_h[(size_t)T_TOTAL * CH];      // fp32 residual
__device__ float g_hT[(size_t)T_TOTAL * CH];     // tf32-rounded shadow of h
__device__ float g_acts[(size_t)T_TOTAL * CH];   // tf32-rounded
__device__ float g_skip[(size_t)T_TOTAL * CH];   // fp32
__device__ float g_spectT[(size_t)T_TOTAL * MEL];// tf32-rounded spect
__device__ float g_wTA[(size_t)8 * 512 * 1408];  // [layer][n][k] tf32
__device__ float g_wTB[(size_t)7 * 512 * 256];   // [layer][n][k] tf32
__device__ float g_wTL[(size_t)256 * 256];       // [n][k] tf32

// ---------------- helpers ---------------------------------------------------
__device__ __forceinline__ uint32_t smem_u32(const void* p) {
    uint32_t a;
    asm("{ .reg .u64 t; cvta.to.shared.u64 t, %1; cvt.u32.u64 %0, t; }" : "=r"(a) : "l"(p));
    return a;
}
__device__ __forceinline__ uint32_t f2tf(float x) {
    uint32_t r; asm("cvt.rna.tf32.f32 %0, %1;" : "=r"(r) : "f"(x)); return r;
}
__device__ __forceinline__ float rtf(float x) { return __uint_as_float(f2tf(x)); }

#define CP16(dst, src, sz) \
    asm volatile("cp.async.cg.shared.global [%0], [%1], 16, %2;" \
        :: "r"(dst), "l"(src), "r"(sz) : "memory")
#define CP_COMMIT() asm volatile("cp.async.commit_group;" ::: "memory")
#define CP_WAIT(n)  asm volatile("cp.async.wait_group %0;" :: "n"(n) : "memory")

__device__ __forceinline__ void mma8(float* d, const uint32_t* a, const uint32_t* b) {
    asm volatile(
        "mma.sync.aligned.m16n8k8.row.col.f32.tf32.tf32.f32 "
        "{%0,%1,%2,%3}, {%4,%5,%6,%7}, {%8,%9}, {%0,%1,%2,%3};"
        : "+f"(d[0]), "+f"(d[1]), "+f"(d[2]), "+f"(d[3])
        : "r"(a[0]), "r"(a[1]), "r"(a[2]), "r"(a[3]), "r"(b[0]), "r"(b[1]));
}

#define AST 36   // smem row stride in floats (32 k + 4 pad)

// ---- big-tile layout (layerA / layerB): A 128 rows, B 256 rows -------------
#define OFF_A2(buf) ((buf) * 55296)
#define OFF_B2(buf) (18432 + (buf) * 55296)
#define OFF_BIAS2   110592
#define SMEM_AB2    112640

// ---- small layout (layerL): A 128 rows, B 128 rows -------------------------
#define OFFL_A(buf) ((buf) * 36864)
#define OFFL_B(buf) (18432 + (buf) * 36864)
#define OFFL_BIAS   73728
#define SMEM_L      75776

// ---------------------------------------------------------------------------
// start: h = audio @ start_w + start_b ; hT = tf32(h) ; skip = 0
// ---------------------------------------------------------------------------
__global__ void start_kernel(const float* __restrict__ audio,
                             const float* __restrict__ sw,
                             const float* __restrict__ sb) {
    int idx = blockIdx.x * blockDim.x + threadIdx.x;
    int t = idx >> 8;
    int c = idx & 255;
    float4 a = *(const float4*)&audio[(size_t)t * 4];
    float v = sb[c] + a.x * sw[c] + a.y * sw[256 + c] + a.z * sw[512 + c] + a.w * sw[768 + c];
    g_h[idx] = v;
    g_hT[idx] = rtf(v);
    g_skip[idx] = 0.f;
}

__global__ void round_spect_kernel(const float* __restrict__ spect) {
    size_t idx = (size_t)blockIdx.x * blockDim.x + threadIdx.x;
    g_spectT[idx] = rtf(spect[idx]);
}

// weight transposes: [k][n] -> [n][k], tf32-rounded
__global__ void transA_kernel(const float* __restrict__ in_w, const float* __restrict__ cond_w) {
    size_t idx = (size_t)blockIdx.x * blockDim.x + threadIdx.x;   // 8*512*1408
    int k = (int)(idx % 1408);
    size_t t = idx / 1408;
    int n = (int)(t % 512);
    int l = (int)(t / 512);
    float v;
    if (k < 768)
        v = in_w[(((size_t)l * 3 + (k >> 8)) * 256 + (k & 255)) * 512 + n];
    else
        v = cond_w[((size_t)l * 640 + (k - 768)) * 512 + n];
    g_wTA[idx] = rtf(v);
}
__global__ void transB_kernel(const float* __restrict__ rsw) {
    size_t idx = (size_t)blockIdx.x * blockDim.x + threadIdx.x;   // 7*512*256
    int k = (int)(idx & 255);
    size_t t = idx >> 8;
    int n = (int)(t % 512);
    int l = (int)(t / 512);
    g_wTB[idx] = rtf(rsw[((size_t)l * 256 + k) * 512 + n]);
}
__global__ void transL_kernel(const float* __restrict__ rlw) {
    int idx = blockIdx.x * blockDim.x + threadIdx.x;              // 256*256
    int k = idx & 255;
    int n = idx >> 8;
    g_wTL[idx] = rtf(rlw[k * 256 + n]);
}

// ---------------------------------------------------------------------------
// big-tile compute: warp tile 64 (M) x 64 (B-rows), d[4][8][4]
// As: 128 rows x 32 k ; Bs: 256 rows x 32 k (pair-interleaved halves)
// ---------------------------------------------------------------------------
__device__ __forceinline__ void compute_stage2(const float* As, const float* Bs,
                                               int wm, int wn, int lane,
                                               float d[4][8][4]) {
    const int ar = lane >> 2;
    const int ac = lane & 3;
    #pragma unroll
    for (int q = 0; q < 4; q++) {
        const int k0 = q * 8;
        uint32_t a[4][4];
        #pragma unroll
        for (int mi = 0; mi < 4; mi++) {
            int mb = wm * 64 + mi * 16 + ar;
            a[mi][0] = __float_as_uint(As[mb * AST + k0 + ac]);
            a[mi][1] = __float_as_uint(As[(mb + 8) * AST + k0 + ac]);
            a[mi][2] = __float_as_uint(As[mb * AST + k0 + ac + 4]);
            a[mi][3] = __float_as_uint(As[(mb + 8) * AST + k0 + ac + 4]);
        }
        #pragma unroll
        for (int ni = 0; ni < 8; ni++) {
            int nb = wn * 64 + ni * 8 + ar;
            uint32_t b[2];
            b[0] = __float_as_uint(Bs[nb * AST + k0 + ac]);
            b[1] = __float_as_uint(Bs[nb * AST + k0 + ac + 4]);
            #pragma unroll
            for (int mi = 0; mi < 4; mi++) mma8(d[mi][ni], a[mi], b);
        }
    }
}

// ---------------------------------------------------------------------------
// layer A: x = conv(h)+cond+biases ; acts = tf32(tanh(xa)*sigmoid(xb))
// CTA: 128 tokens x 256 B-rows (=128 act cols, halves interleaved). grid (512,2)
// ---------------------------------------------------------------------------
__global__ void __launch_bounds__(256, 1) layerA_mma(
    const float* __restrict__ in_b, const float* __restrict__ cond_b,
    int layer, int dil) {
    extern __shared__ char smem[];
    const uint32_t sbase = smem_u32(smem);
    const int tid = threadIdx.x;
    const int lane = tid & 31;
    const int wid = tid >> 5;
    const int wm = wid >> 2;     // 0..1
    const int wn = wid & 3;      // 0..3
    const int row0 = blockIdx.x * 128;
    const int n0 = blockIdx.y * 128;      // act-col base (0 or 128)
    const float* __restrict__ wT = g_wTA + (size_t)layer * 512 * 1408;

    {   // biases (full 512 of this layer)
        float* bsm = (float*)(smem + OFF_BIAS2);
        bsm[tid] = in_b[layer * 512 + tid] + cond_b[layer * 512 + tid];
        bsm[256 + tid] = in_b[layer * 512 + 256 + tid] + cond_b[layer * 512 + 256 + tid];
    }

    auto load_stage = [&](int s, int buf) {
        const int kk0 = s * 32;
        const uint32_t abase = sbase + OFF_A2(buf);
        const uint32_t bbase = sbase + OFF_B2(buf);
        if (kk0 < 768) {
            const int tap = kk0 >> 8, kc = kk0 & 255;
            const int shift = (tap - 1) * dil;
            #pragma unroll
            for (int i = 0; i < 4; i++) {
                int v = tid + i * 256;
                int row = v >> 3, c8 = v & 7;
                int r = row0 + row;
                int ts = (r & (T_BATCH - 1)) + shift;
                const float* src;
                uint32_t sz;
                if ((unsigned)ts < (unsigned)T_BATCH) {
                    src = g_hT + (size_t)(r + shift) * CH + kc + c8 * 4;
                    sz = 16;
                } else {
                    src = g_hT;
                    sz = 0;
                }
                CP16(abase + row * 144 + c8 * 16, src, sz);
            }
        } else {
            const int km = kk0 - 768;
            #pragma unroll
            for (int i = 0; i < 4; i++) {
                int v = tid + i * 256;
                int row = v >> 3, c8 = v & 7;
                const float* src = g_spectT + (size_t)(row0 + row) * MEL + km + c8 * 4;
                CP16(abase + row * 144 + c8 * 16, src, 16);
            }
        }
        #pragma unroll
        for (int i = 0; i < 8; i++) {
            int v = tid + i * 256;
            int nl = v >> 3, c8 = v & 7;        // nl 0..255
            int ng = n0 + (nl >> 1) + (nl & 1) * 256;  // pair-interleave halves
            const float* src = wT + (size_t)ng * 1408 + kk0 + c8 * 4;
            CP16(bbase + nl * 144 + c8 * 16, src, 16);
        }
        CP_COMMIT();
    };

    float d[4][8][4] = {};

    load_stage(0, 0);
    for (int s = 0; s < 44; s++) {
        if (s + 1 < 44) { load_stage(s + 1, (s + 1) & 1); CP_WAIT(1); }
        else CP_WAIT(0);
        __syncthreads();
        compute_stage2((const float*)(smem + OFF_A2(s & 1)),
                       (const float*)(smem + OFF_B2(s & 1)), wm, wn, lane, d);
        __syncthreads();
    }

    const float* bsm = (const float*)(smem + OFF_BIAS2);
    const int ar = lane >> 2, ac = lane & 3;
    #pragma unroll
    for (int mi = 0; mi < 4; mi++) {
        #pragma unroll
        for (int eh = 0; eh < 2; eh++) {
            const int m = row0 + wm * 64 + mi * 16 + ar + eh * 8;
            #pragma unroll
            for (int ni = 0; ni < 8; ni++) {
                const int j = n0 + wn * 32 + ni * 4 + ac;
                float xa = d[mi][ni][eh * 2 + 0] + bsm[j];
                float xb = d[mi][ni][eh * 2 + 1] + bsm[256 + j];
                g_acts[(size_t)m * CH + j] = rtf(tanhf(xa) * (1.f / (1.f + expf(-xb))));
            }
        }
    }
}

// ---------------------------------------------------------------------------
// layer B: rs = acts@w + b ; h += rs[:, :256] (fp32 + tf32 shadow); skip += rs[:, 256:]
// ---------------------------------------------------------------------------
__global__ void __launch_bounds__(256, 1) layerB_mma(
    const float* __restrict__ rs_b, int layer) {
    extern __shared__ char smem[];
    const uint32_t sbase = smem_u32(smem);
    const int tid = threadIdx.x;
    const int lane = tid & 31;
    const int wid = tid >> 5;
    const int wm = wid >> 2;
    const int wn = wid & 3;
    const int row0 = blockIdx.x * 128;
    const int n0 = blockIdx.y * 128;
    const float* __restrict__ wT = g_wTB + (size_t)layer * 512 * 256;

    {
        float* bsm = (float*)(smem + OFF_BIAS2);
        bsm[tid] = rs_b[layer * 512 + tid];
        bsm[256 + tid] = rs_b[layer * 512 + 256 + tid];
    }

    auto load_stage = [&](int s, int buf) {
        const int kk0 = s * 32;
        const uint32_t abase = sbase + OFF_A2(buf);
        const uint32_t bbase = sbase + OFF_B2(buf);
        #pragma unroll
        for (int i = 0; i < 4; i++) {
            int v = tid + i * 256;
            int row = v >> 3, c8 = v & 7;
            const float* src = g_acts + (size_t)(row0 + row) * CH + kk0 + c8 * 4;
            CP16(abase + row * 144 + c8 * 16, src, 16);
        }
        #pragma unroll
        for (int i = 0; i < 8; i++) {
            int v = tid + i * 256;
            int nl = v >> 3, c8 = v & 7;
            int ng = n0 + (nl >> 1) + (nl & 1) * 256;
            const float* src = wT + (size_t)ng * 256 + kk0 + c8 * 4;
            CP16(bbase + nl * 144 + c8 * 16, src, 16);
        }
        CP_COMMIT();
    };

    float d[4][8][4] = {};

    load_stage(0, 0);
    for (int s = 0; s < 8; s++) {
        if (s + 1 < 8) { load_stage(s + 1, (s + 1) & 1); CP_WAIT(1); }
        else CP_WAIT(0);
        __syncthreads();
        compute_stage2((const float*)(smem + OFF_A2(s & 1)),
                       (const float*)(smem + OFF_B2(s & 1)), wm, wn, lane, d);
        __syncthreads();
    }

    const float* bsm = (const float*)(smem + OFF_BIAS2);
    const int ar = lane >> 2, ac = lane & 3;
    #pragma unroll
    for (int mi = 0; mi < 4; mi++) {
        #pragma unroll
        for (int eh = 0; eh < 2; eh++) {
            const int m = row0 + wm * 64 + mi * 16 + ar + eh * 8;
            #pragma unroll
            for (int ni = 0; ni < 8; ni++) {
                const int j = n0 + wn * 32 + ni * 4 + ac;
                const size_t o = (size_t)m * CH + j;
                float hv = g_h[o] + d[mi][ni][eh * 2 + 0] + bsm[j];
                float sv = g_skip[o] + d[mi][ni][eh * 2 + 1] + bsm[256 + j];
                g_h[o] = hv;
                g_hT[o] = rtf(hv);
                g_skip[o] = sv;
            }
        }
    }
}

// ---------------------------------------------------------------------------
// last layer: skip += acts @ res_last_w + res_last_b (N=256)
// ---------------------------------------------------------------------------
__device__ __forceinline__ void compute_stageL(const float* As, const float* Bs,
                                               int wm, int wn, int lane,
                                               float d[2][4][4]) {
    const int ar = lane >> 2;
    const int ac = lane & 3;
    #pragma unroll
    for (int q = 0; q < 4; q++) {
        const int k0 = q * 8;
        uint32_t a[2][4];
        #pragma unroll
        for (int mi = 0; mi < 2; mi++) {
            int mb = wm * 32 + mi * 16 + ar;
            a[mi][0] = __float_as_uint(As[mb * AST + k0 + ac]);
            a[mi][1] = __float_as_uint(As[(mb + 8) * AST + k0 + ac]);
            a[mi][2] = __float_as_uint(As[mb * AST + k0 + ac + 4]);
            a[mi][3] = __float_as_uint(As[(mb + 8) * AST + k0 + ac + 4]);
        }
        #pragma unroll
        for (int ni = 0; ni < 4; ni++) {
            int nb = wn * 32 + ni * 8 + ar;
            uint32_t b[2];
            b[0] = __float_as_uint(Bs[nb * AST + k0 + ac]);
            b[1] = __float_as_uint(Bs[nb * AST + k0 + ac + 4]);
            mma8(d[0][ni], a[0], b);
            mma8(d[1][ni], a[1], b);
        }
    }
}

__global__ void __launch_bounds__(256, 2) layerL_mma(const float* __restrict__ rl_b) {
    extern __shared__ char smem[];
    const uint32_t sbase = smem_u32(smem);
    const int tid = threadIdx.x;
    const int lane = tid & 31;
    const int wid = tid >> 5;
    const int wm = wid & 3;
    const int wn = wid >> 2;
    const int row0 = blockIdx.x * 128;
    const int n0 = blockIdx.y * 64;

    {
        float* bsm = (float*)(smem + OFFL_BIAS);
        bsm[tid] = rl_b[tid];
    }

    auto load_stage = [&](int s, int buf) {
        const int kk0 = s * 32;
        const uint32_t abase = sbase + OFFL_A(buf);
        const uint32_t bbase = sbase + OFFL_B(buf);
        #pragma unroll
        for (int i = 0; i < 4; i++) {
            int v = tid + i * 256;
            int row = v >> 3, c8 = v & 7;
            const float* src = g_acts + (size_t)(row0 + row) * CH + kk0 + c8 * 4;
            CP16(abase + row * 144 + c8 * 16, src, 16);
        }
        #pragma unroll
        for (int i = 0; i < 2; i++) {
            int v = tid + i * 256;
            int nl = v >> 3, c8 = v & 7;   // nl 0..63
            const float* src = g_wTL + (size_t)(n0 + nl) * 256 + kk0 + c8 * 4;
            CP16(bbase + nl * 144 + c8 * 16, src, 16);
        }
        CP_COMMIT();
    };

    float d[2][4][4] = {};

    load_stage(0, 0);
    for (int s = 0; s < 8; s++) {
        if (s + 1 < 8) { load_stage(s + 1, (s + 1) & 1); CP_WAIT(1); }
        else CP_WAIT(0);
        __syncthreads();
        compute_stageL((const float*)(smem + OFFL_A(s & 1)),
                       (const float*)(smem + OFFL_B(s & 1)), wm, wn, lane, d);
        __syncthreads();
    }

    const float* bsm = (const float*)(smem + OFFL_BIAS);
    #pragma unroll
    for (int mi = 0; mi < 2; mi++) {
        #pragma unroll
        for (int eh = 0; eh < 2; eh++) {
            const int m = row0 + wm * 32 + mi * 16 + (lane >> 2) + eh * 8;
            #pragma unroll
            for (int ni = 0; ni < 4; ni++) {
                const int j = n0 + wn * 32 + ni * 8 + (lane & 3) * 2;
                const size_t o = (size_t)m * CH + j;
                float2 sv = *(float2*)&g_skip[o];
                sv.x += d[mi][ni][eh * 2 + 0] + bsm[j];
                sv.y += d[mi][ni][eh * 2 + 1] + bsm[j + 1];
                *(float2*)&g_skip[o] = sv;
            }
        }
    }
}

// ---------------------------------------------------------------------------
// end: out = skip @ end_w + end_b  — one thread per token, ew cached in smem
// ---------------------------------------------------------------------------
__global__ void end_kernel(const float* __restrict__ ew,
                           const float* __restrict__ eb,
                           float* __restrict__ out) {
    __shared__ float ews[2048];
    __shared__ float ebs[8];
    const int tid = threadIdx.x;
    #pragma unroll
    for (int i = 0; i < 8; i++) ews[tid + i * 256] = ew[tid + i * 256];
    if (tid < 8) ebs[tid] = eb[tid];
    __syncthreads();

    const int t = blockIdx.x * blockDim.x + tid;
    const float* s = &g_skip[(size_t)t * CH];
    float acc[8];
    #pragma unroll
    for (int o = 0; o < 8; o++) acc[o] = ebs[o];
    for (int c = 0; c < CH; c += 4) {
        float4 sv = *(const float4*)&s[c];
        #pragma unroll
        for (int e = 0; e < 4; e++) {
            float svv = (&sv.x)[e];
            const float* w = &ews[(c + e) * 8];
            #pragma unroll
            for (int o = 0; o < 8; o++) acc[o] += svv * w[o];
        }
    }
    float4* op = (float4*)&out[(size_t)t * 8];
    op[0] = make_float4(acc[0], acc[1], acc[2], acc[3]);
    op[1] = make_float4(acc[4], acc[5], acc[6], acc[7]);
}

// ---------------------------------------------------------------------------
extern "C" void kernel_launch(void* const* d_in, const int* in_sizes, int n_in,
                              void* d_out, int out_size) {
    const float* audio      = (const float*)d_in[0];
    const float* spect      = (const float*)d_in[1];
    const float* start_w    = (const float*)d_in[2];
    const float* start_b    = (const float*)d_in[3];
    const float* in_w       = (const float*)d_in[4];
    const float* in_b       = (const float*)d_in[5];
    const float* cond_w     = (const float*)d_in[6];
    const float* cond_b     = (const float*)d_in[7];
    const float* res_skip_w = (const float*)d_in[8];
    const float* res_skip_b = (const float*)d_in[9];
    const float* res_last_w = (const float*)d_in[10];
    const float* res_last_b = (const float*)d_in[11];
    const float* end_w      = (const float*)d_in[12];
    const float* end_b      = (const float*)d_in[13];
    float* out = (float*)d_out;

    // Idempotent, called every time (no static guards per harness contract).
    cudaFuncSetAttribute(layerA_mma, cudaFuncAttributeMaxDynamicSharedMemorySize, SMEM_AB2);
    cudaFuncSetAttribute(layerB_mma, cudaFuncAttributeMaxDynamicSharedMemorySize, SMEM_AB2);
    cudaFuncSetAttribute(layerL_mma, cudaFuncAttributeMaxDynamicSharedMemorySize, SMEM_L);

    start_kernel<<<(T_TOTAL * CH) / 256, 256>>>(audio, start_w, start_b);
    round_spect_kernel<<<(T_TOTAL / 256) * MEL, 256>>>(spect);
    transA_kernel<<<22528, 256>>>(in_w, cond_w);
    transB_kernel<<<3584, 256>>>(res_skip_w);
    transL_kernel<<<256, 256>>>(res_last_w);

    dim3 g2(512, 2);
    dim3 g4(512, 4);
    for (int l = 0; l < 8; l++) {
        layerA_mma<<<g2, 256, SMEM_AB2>>>(in_b, cond_b, l, 1 << l);
        if (l < 7)
            layerB_mma<<<g2, 256, SMEM_AB2>>>(res_skip_b, l);
        else
            layerL_mma<<<g4, 256, SMEM_L>>>(res_last_b);
    }

    end_kernel<<<T_TOTAL / 256, 256>>>(end_w, end_b, out);
}

// round 10
// speedup vs baseline: 1.9723x; 1.9700x over previous
#include <cuda_runtime.h>
#include <cuda_fp16.h>
#include <cstdint>
#include <math.h>

#define T_TOTAL 65536
#define T_BATCH 8192
#define CH 256
#define MEL 640

// ---------------- scratch (__device__ globals) ------------------------------
__device__ float  g_h[(size_t)T_TOTAL * CH];       // fp32 residual
__device__ float  g_skip[(size_t)T_TOTAL * CH];    // fp32 skip accumulator
__device__ __half g_hH[(size_t)T_TOTAL * CH];      // fp16 shadow of h
__device__ __half g_actsH[(size_t)T_TOTAL * CH];   // fp16 activations
__device__ __half g_spectH[(size_t)T_TOTAL * MEL]; // fp16 spect
__device__ __half g_wA[(size_t)8 * 512 * 1408];    // [layer][n][k]
__device__ __half g_wB[(size_t)7 * 512 * 256];     // [layer][n][k]
__device__ __half g_wL[(size_t)256 * 256];         // [n][k]

// ---------------- helpers ---------------------------------------------------
__device__ __forceinline__ uint32_t smem_u32(const void* p) {
    uint32_t a;
    asm("{ .reg .u64 t; cvta.to.shared.u64 t, %1; cvt.u32.u64 %0, t; }" : "=r"(a) : "l"(p));
    return a;
}

#define CP16(dst, src, sz) \
    asm volatile("cp.async.cg.shared.global [%0], [%1], 16, %2;" \
        :: "r"(dst), "l"(src), "r"(sz) : "memory")
#define CP_COMMIT() asm volatile("cp.async.commit_group;" ::: "memory")
#define CP_WAIT(n)  asm volatile("cp.async.wait_group %0;" :: "n"(n) : "memory")

__device__ __forceinline__ void mma16(float* d, const uint32_t* a, const uint32_t* b) {
    asm volatile(
        "mma.sync.aligned.m16n8k16.row.col.f32.f16.f16.f32 "
        "{%0,%1,%2,%3}, {%4,%5,%6,%7}, {%8,%9}, {%0,%1,%2,%3};"
        : "+f"(d[0]), "+f"(d[1]), "+f"(d[2]), "+f"(d[3])
        : "r"(a[0]), "r"(a[1]), "r"(a[2]), "r"(a[3]), "r"(b[0]), "r"(b[1]));
}

#define HST 72   // smem row stride in halves (64 data + 8 pad = 144 B, 16B mult)

// ---- layerA/B layout: A 128 rows x 144B, B 128 rows x 144B -----------------
#define OFF_A(buf) ((buf) * 36864)
#define OFF_B(buf) (18432 + (buf) * 36864)
#define OFF_BIAS   73728
#define SMEM_AB    75776
// ---- layerL: A 128 rows, B 64 rows ------------------------------------------
#define OFFL_A(buf) ((buf) * 27648)
#define OFFL_B(buf) (18432 + (buf) * 27648)
#define OFFL_BIAS   55296
#define SMEM_L      56320

// ---------------------------------------------------------------------------
// prepW: all weights -> [n][k] fp16 (single launch)
// ---------------------------------------------------------------------------
#define NA (8u * 512u * 1408u)   // 5767168
#define NB (7u * 512u * 256u)    // 917504
#define NL (256u * 256u)         // 65536
__global__ void prepW_kernel(const float* __restrict__ in_w,
                             const float* __restrict__ cond_w,
                             const float* __restrict__ rsw,
                             const float* __restrict__ rlw) {
    uint32_t idx = blockIdx.x * blockDim.x + threadIdx.x;  // NA+NB+NL total
    if (idx < NA) {
        int k = (int)(idx % 1408u);
        uint32_t t = idx / 1408u;
        int n = (int)(t & 511u);
        int l = (int)(t >> 9);
        float v;
        if (k < 768)
            v = in_w[(((size_t)l * 3 + (k >> 8)) * 256 + (k & 255)) * 512 + n];
        else
            v = cond_w[((size_t)l * 640 + (k - 768)) * 512 + n];
        g_wA[idx] = __float2half_rn(v);
    } else if (idx < NA + NB) {
        uint32_t r = idx - NA;
        int k = (int)(r & 255u);
        uint32_t t = r >> 8;
        int n = (int)(t & 511u);
        int l = (int)(t >> 9);
        g_wB[r] = __float2half_rn(rsw[((size_t)l * 256 + k) * 512 + n]);
    } else if (idx < NA + NB + NL) {
        uint32_t r = idx - NA - NB;
        int k = (int)(r & 255u);
        int n = (int)(r >> 8);
        g_wL[r] = __float2half_rn(rlw[k * 256 + n]);
    }
}

// ---------------------------------------------------------------------------
// start: h = audio @ start_w + start_b ; hH = fp16(h); skip = 0
// ---------------------------------------------------------------------------
__global__ void start_kernel(const float* __restrict__ audio,
                             const float* __restrict__ sw,
                             const float* __restrict__ sb) {
    int idx = blockIdx.x * blockDim.x + threadIdx.x;
    int t = idx >> 8;
    int c = idx & 255;
    float4 a = *(const float4*)&audio[(size_t)t * 4];
    float v = sb[c] + a.x * sw[c] + a.y * sw[256 + c] + a.z * sw[512 + c] + a.w * sw[768 + c];
    g_h[idx] = v;
    g_hH[idx] = __float2half_rn(v);
    g_skip[idx] = 0.f;
}

__global__ void prepS_kernel(const float* __restrict__ spect) {
    size_t idx = (size_t)blockIdx.x * blockDim.x + threadIdx.x;
    g_spectH[idx] = __float2half_rn(spect[idx]);
}

// ---------------------------------------------------------------------------
// fp16 compute: warp 32 (M) x 32 (N) per gate half; BK=64 (4 k16 steps)
// As: 128 rows x HST ; Bs: 128 rows x HST (rows 0-63 half0, 64-127 half1)
// ---------------------------------------------------------------------------
__device__ __forceinline__ void compute_f16(const __half* As, const __half* Bs,
                                            int wm, int wn, int lane,
                                            float d[2][2][4][4], int nhalves) {
    const int ar = lane >> 2;
    const int ac2 = (lane & 3) * 2;
    #pragma unroll
    for (int q = 0; q < 4; q++) {
        const int k0 = q * 16;
        uint32_t a[2][4];
        #pragma unroll
        for (int mi = 0; mi < 2; mi++) {
            int mb = wm * 32 + mi * 16 + ar;
            a[mi][0] = *(const uint32_t*)&As[mb * HST + k0 + ac2];
            a[mi][1] = *(const uint32_t*)&As[(mb + 8) * HST + k0 + ac2];
            a[mi][2] = *(const uint32_t*)&As[mb * HST + k0 + 8 + ac2];
            a[mi][3] = *(const uint32_t*)&As[(mb + 8) * HST + k0 + 8 + ac2];
        }
        #pragma unroll
        for (int t = 0; t < 2; t++) {
            if (t >= nhalves) break;
            #pragma unroll
            for (int ni = 0; ni < 4; ni++) {
                int nb = t * 64 + wn * 32 + ni * 8 + ar;
                uint32_t b[2];
                b[0] = *(const uint32_t*)&Bs[nb * HST + k0 + ac2];
                b[1] = *(const uint32_t*)&Bs[nb * HST + k0 + 8 + ac2];
                mma16(d[t][0][ni], a[0], b);
                mma16(d[t][1][ni], a[1], b);
            }
        }
    }
}

// ---------------------------------------------------------------------------
// layer A: x = conv(h)+cond+biases ; actsH = fp16(tanh(xa)*sigmoid(xb))
// CTA 128 tokens x 64 cols per half. grid (512, 4). K=1408 in 22 stages of 64.
// ---------------------------------------------------------------------------
__global__ void __launch_bounds__(256, 2) layerA_mma(
    const float* __restrict__ in_b, const float* __restrict__ cond_b,
    int layer, int dil) {
    extern __shared__ char smem[];
    const uint32_t sbase = smem_u32(smem);
    const int tid = threadIdx.x;
    const int lane = tid & 31;
    const int wid = tid >> 5;
    const int wm = wid & 3;
    const int wn = wid >> 2;
    const int row0 = blockIdx.x * 128;
    const int n0 = blockIdx.y * 64;
    const __half* __restrict__ wT = g_wA + (size_t)layer * 512 * 1408;

    {   // biases
        float* bsm = (float*)(smem + OFF_BIAS);
        bsm[tid] = in_b[layer * 512 + tid] + cond_b[layer * 512 + tid];
        bsm[256 + tid] = in_b[layer * 512 + 256 + tid] + cond_b[layer * 512 + 256 + tid];
    }

    // staging: A 128 rows x 8 chunks(16B) + B 128 rows x 8 chunks = 4+4 per thread
    auto load_stage = [&](int s, int buf) {
        const int kk0 = s * 64;
        const uint32_t abase = sbase + OFF_A(buf);
        const uint32_t bbase = sbase + OFF_B(buf);
        if (kk0 < 768) {
            const int tap = kk0 >> 8, kc = kk0 & 255;
            const int shift = (tap - 1) * dil;
            #pragma unroll
            for (int i = 0; i < 4; i++) {
                int v = tid + i * 256;
                int row = v >> 3, c8 = v & 7;
                int r = row0 + row;
                int ts = (r & (T_BATCH - 1)) + shift;
                const __half* src;
                uint32_t sz;
                if ((unsigned)ts < (unsigned)T_BATCH) {
                    src = g_hH + (size_t)(r + shift) * CH + kc + c8 * 8;
                    sz = 16;
                } else {
                    src = g_hH;
                    sz = 0;
                }
                CP16(abase + row * 144 + c8 * 16, src, sz);
            }
        } else {
            const int km = kk0 - 768;
            #pragma unroll
            for (int i = 0; i < 4; i++) {
                int v = tid + i * 256;
                int row = v >> 3, c8 = v & 7;
                const __half* src = g_spectH + (size_t)(row0 + row) * MEL + km + c8 * 8;
                CP16(abase + row * 144 + c8 * 16, src, 16);
            }
        }
        #pragma unroll
        for (int i = 0; i < 4; i++) {
            int v = tid + i * 256;
            int nl = v >> 3, c8 = v & 7;
            int ng = (nl < 64) ? (n0 + nl) : (n0 + 256 + nl - 64);
            const __half* src = wT + (size_t)ng * 1408 + kk0 + c8 * 8;
            CP16(bbase + nl * 144 + c8 * 16, src, 16);
        }
        CP_COMMIT();
    };

    float d[2][2][4][4] = {};

    load_stage(0, 0);
    for (int s = 0; s < 22; s++) {
        CP_WAIT(0);
        __syncthreads();
        if (s + 1 < 22) load_stage(s + 1, (s + 1) & 1);
        compute_f16((const __half*)(smem + OFF_A(s & 1)),
                    (const __half*)(smem + OFF_B(s & 1)), wm, wn, lane, d, 2);
    }

    __syncthreads();
    const float* bsm = (const float*)(smem + OFF_BIAS);
    const int ar = lane >> 2, ac = lane & 3;
    #pragma unroll
    for (int mi = 0; mi < 2; mi++) {
        #pragma unroll
        for (int eh = 0; eh < 2; eh++) {
            const int m = row0 + wm * 32 + mi * 16 + ar + eh * 8;
            #pragma unroll
            for (int ni = 0; ni < 4; ni++) {
                const int j = n0 + wn * 32 + ni * 8 + ac * 2;
                float xa0 = d[0][mi][ni][eh * 2 + 0] + bsm[j];
                float xa1 = d[0][mi][ni][eh * 2 + 1] + bsm[j + 1];
                float xb0 = d[1][mi][ni][eh * 2 + 0] + bsm[256 + j];
                float xb1 = d[1][mi][ni][eh * 2 + 1] + bsm[256 + j + 1];
                float o0 = tanhf(xa0) * (1.f / (1.f + expf(-xb0)));
                float o1 = tanhf(xa1) * (1.f / (1.f + expf(-xb1)));
                *(__half2*)&g_actsH[(size_t)m * CH + j] = __floats2half2_rn(o0, o1);
            }
        }
    }
}

// ---------------------------------------------------------------------------
// layer B: rs = acts@w + b ; h += rs[:,:256] (+fp16 shadow); skip += rs[:,256:]
// K=256 in 4 stages of 64.
// ---------------------------------------------------------------------------
__global__ void __launch_bounds__(256, 2) layerB_mma(
    const float* __restrict__ rs_b, int layer) {
    extern __shared__ char smem[];
    const uint32_t sbase = smem_u32(smem);
    const int tid = threadIdx.x;
    const int lane = tid & 31;
    const int wid = tid >> 5;
    const int wm = wid & 3;
    const int wn = wid >> 2;
    const int row0 = blockIdx.x * 128;
    const int n0 = blockIdx.y * 64;
    const __half* __restrict__ wT = g_wB + (size_t)layer * 512 * 256;

    {
        float* bsm = (float*)(smem + OFF_BIAS);
        bsm[tid] = rs_b[layer * 512 + tid];
        bsm[256 + tid] = rs_b[layer * 512 + 256 + tid];
    }

    auto load_stage = [&](int s, int buf) {
        const int kk0 = s * 64;
        const uint32_t abase = sbase + OFF_A(buf);
        const uint32_t bbase = sbase + OFF_B(buf);
        #pragma unroll
        for (int i = 0; i < 4; i++) {
            int v = tid + i * 256;
            int row = v >> 3, c8 = v & 7;
            const __half* src = g_actsH + (size_t)(row0 + row) * CH + kk0 + c8 * 8;
            CP16(abase + row * 144 + c8 * 16, src, 16);
        }
        #pragma unroll
        for (int i = 0; i < 4; i++) {
            int v = tid + i * 256;
            int nl = v >> 3, c8 = v & 7;
            int ng = (nl < 64) ? (n0 + nl) : (n0 + 256 + nl - 64);
            const __half* src = wT + (size_t)ng * 256 + kk0 + c8 * 8;
            CP16(bbase + nl * 144 + c8 * 16, src, 16);
        }
        CP_COMMIT();
    };

    float d[2][2][4][4] = {};

    load_stage(0, 0);
    for (int s = 0; s < 4; s++) {
        CP_WAIT(0);
        __syncthreads();
        if (s + 1 < 4) load_stage(s + 1, (s + 1) & 1);
        compute_f16((const __half*)(smem + OFF_A(s & 1)),
                    (const __half*)(smem + OFF_B(s & 1)), wm, wn, lane, d, 2);
    }

    __syncthreads();
    const float* bsm = (const float*)(smem + OFF_BIAS);
    const int ar = lane >> 2, ac = lane & 3;
    #pragma unroll
    for (int mi = 0; mi < 2; mi++) {
        #pragma unroll
        for (int eh = 0; eh < 2; eh++) {
            const int m = row0 + wm * 32 + mi * 16 + ar + eh * 8;
            #pragma unroll
            for (int ni = 0; ni < 4; ni++) {
                const int j = n0 + wn * 32 + ni * 8 + ac * 2;
                const size_t o = (size_t)m * CH + j;
                float2 hv = *(float2*)&g_h[o];
                float2 sv = *(float2*)&g_skip[o];
                hv.x += d[0][mi][ni][eh * 2 + 0] + bsm[j];
                hv.y += d[0][mi][ni][eh * 2 + 1] + bsm[j + 1];
                sv.x += d[1][mi][ni][eh * 2 + 0] + bsm[256 + j];
                sv.y += d[1][mi][ni][eh * 2 + 1] + bsm[256 + j + 1];
                *(float2*)&g_h[o] = hv;
                *(__half2*)&g_hH[o] = __floats2half2_rn(hv.x, hv.y);
                *(float2*)&g_skip[o] = sv;
            }
        }
    }
}

// ---------------------------------------------------------------------------
// last layer: skip += acts @ res_last_w + res_last_b (single half, B 64 rows)
// ---------------------------------------------------------------------------
__global__ void __launch_bounds__(256, 2) layerL_mma(const float* __restrict__ rl_b) {
    extern __shared__ char smem[];
    const uint32_t sbase = smem_u32(smem);
    const int tid = threadIdx.x;
    const int lane = tid & 31;
    const int wid = tid >> 5;
    const int wm = wid & 3;
    const int wn = wid >> 2;
    const int row0 = blockIdx.x * 128;
    const int n0 = blockIdx.y * 64;

    {
        float* bsm = (float*)(smem + OFFL_BIAS);
        bsm[tid] = rl_b[tid];
    }

    auto load_stage = [&](int s, int buf) {
        const int kk0 = s * 64;
        const uint32_t abase = sbase + OFFL_A(buf);
        const uint32_t bbase = sbase + OFFL_B(buf);
        #pragma unroll
        for (int i = 0; i < 4; i++) {
            int v = tid + i * 256;
            int row = v >> 3, c8 = v & 7;
            const __half* src = g_actsH + (size_t)(row0 + row) * CH + kk0 + c8 * 8;
            CP16(abase + row * 144 + c8 * 16, src, 16);
        }
        #pragma unroll
        for (int i = 0; i < 2; i++) {
            int v = tid + i * 256;
            int nl = v >> 3, c8 = v & 7;   // nl 0..63
            const __half* src = g_wL + (size_t)(n0 + nl) * 256 + kk0 + c8 * 8;
            CP16(bbase + nl * 144 + c8 * 16, src, 16);
        }
        CP_COMMIT();
    };

    float d[2][2][4][4] = {};

    load_stage(0, 0);
    for (int s = 0; s < 4; s++) {
        CP_WAIT(0);
        __syncthreads();
        if (s + 1 < 4) load_stage(s + 1, (s + 1) & 1);
        compute_f16((const __half*)(smem + OFFL_A(s & 1)),
                    (const __half*)(smem + OFFL_B(s & 1)), wm, wn, lane, d, 1);
    }

    __syncthreads();
    const float* bsm = (const float*)(smem + OFFL_BIAS);
    const int ar = lane >> 2, ac = lane & 3;
    #pragma unroll
    for (int mi = 0; mi < 2; mi++) {
        #pragma unroll
        for (int eh = 0; eh < 2; eh++) {
            const int m = row0 + wm * 32 + mi * 16 + ar + eh * 8;
            #pragma unroll
            for (int ni = 0; ni < 4; ni++) {
                const int j = n0 + wn * 32 + ni * 8 + ac * 2;
                const size_t o = (size_t)m * CH + j;
                float2 sv = *(float2*)&g_skip[o];
                sv.x += d[0][mi][ni][eh * 2 + 0] + bsm[j];
                sv.y += d[0][mi][ni][eh * 2 + 1] + bsm[j + 1];
                *(float2*)&g_skip[o] = sv;
            }
        }
    }
}

// ---------------------------------------------------------------------------
// end: out = skip @ end_w + end_b  — one thread per token, ew cached in smem
// ---------------------------------------------------------------------------
__global__ void end_kernel(const float* __restrict__ ew,
                           const float* __restrict__ eb,
                           float* __restrict__ out) {
    __shared__ float ews[2048];
    __shared__ float ebs[8];
    const int tid = threadIdx.x;
    #pragma unroll
    for (int i = 0; i < 8; i++) ews[tid + i * 256] = ew[tid + i * 256];
    if (tid < 8) ebs[tid] = eb[tid];
    __syncthreads();

    const int t = blockIdx.x * blockDim.x + tid;
    const float* s = &g_skip[(size_t)t * CH];
    float acc[8];
    #pragma unroll
    for (int o = 0; o < 8; o++) acc[o] = ebs[o];
    for (int c = 0; c < CH; c += 4) {
        float4 sv = *(const float4*)&s[c];
        #pragma unroll
        for (int e = 0; e < 4; e++) {
            float svv = (&sv.x)[e];
            const float* w = &ews[(c + e) * 8];
            #pragma unroll
            for (int o = 0; o < 8; o++) acc[o] += svv * w[o];
        }
    }
    float4* op = (float4*)&out[(size_t)t * 8];
    op[0] = make_float4(acc[0], acc[1], acc[2], acc[3]);
    op[1] = make_float4(acc[4], acc[5], acc[6], acc[7]);
}

// ---------------------------------------------------------------------------
extern "C" void kernel_launch(void* const* d_in, const int* in_sizes, int n_in,
                              void* d_out, int out_size) {
    const float* audio      = (const float*)d_in[0];
    const float* spect      = (const float*)d_in[1];
    const float* start_w    = (const float*)d_in[2];
    const float* start_b    = (const float*)d_in[3];
    const float* in_w       = (const float*)d_in[4];
    const float* in_b       = (const float*)d_in[5];
    const float* cond_w     = (const float*)d_in[6];
    const float* cond_b     = (const float*)d_in[7];
    const float* res_skip_w = (const float*)d_in[8];
    const float* res_skip_b = (const float*)d_in[9];
    const float* res_last_w = (const float*)d_in[10];
    const float* res_last_b = (const float*)d_in[11];
    const float* end_w      = (const float*)d_in[12];
    const float* end_b      = (const float*)d_in[13];
    float* out = (float*)d_out;

    cudaFuncSetAttribute(layerA_mma, cudaFuncAttributeMaxDynamicSharedMemorySize, SMEM_AB);
    cudaFuncSetAttribute(layerB_mma, cudaFuncAttributeMaxDynamicSharedMemorySize, SMEM_AB);
    cudaFuncSetAttribute(layerL_mma, cudaFuncAttributeMaxDynamicSharedMemorySize, SMEM_L);

    // launch order puts layerA(l=0) in ncu's profiled slot (#4)
    prepW_kernel<<<(NA + NB + NL) / 256, 256>>>(in_w, cond_w, res_skip_w, res_last_w);
    start_kernel<<<(T_TOTAL * CH) / 256, 256>>>(audio, start_w, start_b);
    prepS_kernel<<<(T_TOTAL / 256) * MEL, 256>>>(spect);

    dim3 g4(512, 4);
    for (int l = 0; l < 8; l++) {
        layerA_mma<<<g4, 256, SMEM_AB>>>(in_b, cond_b, l, 1 << l);
        if (l < 7)
            layerB_mma<<<g4, 256, SMEM_AB>>>(res_skip_b, l);
        else
            layerL_mma<<<g4, 256, SMEM_L>>>(res_last_b);
    }

    end_kernel<<<T_TOTAL / 256, 256>>>(end_w, end_b, out);
}